// round 7
// baseline (speedup 1.0000x reference)
#include <cuda_runtime.h>

// SNN forward: B=128, T=1000, F=20, H=256, O=200.
// 1 CTA per batch element, 1024 threads, persistent.
// Warp specialization:
//   warps 0-7  : V1 gather + layer1 update (step t)
//   warps 8-15 : W2T gather + layer2 update (step t-1), ring producer
//   warps 16-23: V2 gather
//   warps 24-31: DECOUPLED readout (WoT gather + softmax), runs 1-3 steps
//                behind via a 4-deep spike-list ring + named-barrier handshake.

#define Bt 128
#define Tt 1000
#define Ft 20
#define Ht 256
#define Ot 200
#define NTHR 1024

// Preprocessed weights (diag-zeroed Vrec, transposed W2/Wout), L2-resident (~968KB).
__device__ __align__(16) float g_V1[Ht * Ht];
__device__ __align__(16) float g_V2[Ht * Ht];
__device__ __align__(16) float g_W2T[Ht * Ht];   // W2T[h][g] = W2[g][h]
__device__ __align__(16) float g_WoT[Ht * Ot];   // WoT[h][o] = Wout[o][h]

__global__ void snn_prep(const float* __restrict__ V1, const float* __restrict__ V2,
                         const float* __restrict__ W2, const float* __restrict__ Wout) {
    int i = blockIdx.x * blockDim.x + threadIdx.x;
    if (i < Ht * Ht) {
        int r = i >> 8, c = i & 255;
        float z = (r == c) ? 0.0f : 1.0f;
        g_V1[i] = V1[i] * z;
        g_V2[i] = V2[i] * z;
        g_W2T[i] = W2[c * Ht + r];
    }
    if (i < Ht * Ot) {
        int h = i / Ot, o = i - h * Ot;
        g_WoT[i] = Wout[o * Ht + h];
    }
}

// Dynamic SMEM layout (float index):
#define OFF_W1T  0        // [5120]   W1^T [F][H]
#define OFF_PA   5120     // [4*256]  V1 partials
#define OFF_PC   6144     // [4*256]  W2T partials
#define OFF_PB   7168     // [4*256]  V2 partials
#define OFF_PW   8192     // [4*256]  WoT partials (readout-private)
#define OFF_L1   9216     // [2*256] int: ping-pong spike list layer1
#define OFF_L2R  9728     // [4*256] int: 4-deep spike-list ring layer2
#define OFF_WC1  10752    // [8] int
#define OFF_WC2  10760    // [8] int
#define OFF_N1C  10768    // [2] int
#define OFF_N2R  10772    // [4] int
#define OFF_WRED 10776    // [8] float softmax scratch
#define OFF_XBUF 10784    // [2*20] x(t) double buffer
#define SMEM_FLOATS (10784 + 40)
#define SMEM_BYTES  (SMEM_FLOATS * 4)

// Named barriers: 0=init syncthreads, 1=layer1(256), 3=layer2(256),
// 12=main gather->update (768), 13=l1 handoff (w0-15, 512),
// 14=l2 handoff (w8-23, 512), 15=readout internal (256),
// 4+s=ring full[s] (512), 8+s=ring free[s] (512).
#define BSYNC(id, n)   asm volatile("bar.sync %0, %1;"   :: "r"(id), "r"(n) : "memory")
#define BARRIVE(id, n) asm volatile("bar.arrive %0, %1;" :: "r"(id), "r"(n) : "memory")

__global__ __launch_bounds__(NTHR, 1)
void snn_main(const float* __restrict__ x, const float* __restrict__ W1,
              const float* __restrict__ b1, const float* __restrict__ beta1,
              const float* __restrict__ b2, const float* __restrict__ beta2,
              const float* __restrict__ alpha_out, const float* __restrict__ beta_out,
              float* __restrict__ out) {
    extern __shared__ float sm[];
    float* w1t  = sm + OFF_W1T;
    float* PA   = sm + OFF_PA;
    float* PC   = sm + OFF_PC;
    float* PB   = sm + OFF_PB;
    float* PW   = sm + OFF_PW;
    int*   l1   = (int*)(sm + OFF_L1);
    int*   l2r  = (int*)(sm + OFF_L2R);
    int*   wc1  = (int*)(sm + OFF_WC1);
    int*   wc2  = (int*)(sm + OFF_WC2);
    int*   n1c  = (int*)(sm + OFF_N1C);
    int*   n2r  = (int*)(sm + OFF_N2R);
    float* wred = sm + OFF_WRED;
    float* xbuf = sm + OFF_XBUF;

    const int tid  = threadIdx.x;
    const int b    = blockIdx.x;
    const int g    = (tid >> 6) & 3;        // group within 256-thread band
    const int lg   = tid & 63;              // float4 column within row
    const int wid  = tid >> 5, lane = tid & 31;
    const float* xb = x + (size_t)b * (Tt * Ft);

    for (int i = tid; i < Ft * Ht; i += NTHR) {       // W1^T [F][H]
        int f = i >> 8, h = i & 255;
        w1t[i] = W1[h * Ft + f];
    }
    if (tid < 2) n1c[tid] = 0;
    if (tid < 4) n2r[tid] = 0;
    for (int i = tid; i < 1024; i += NTHR) PB[i] = 0.f;   // read at t=1 before first V2 gather
    if (tid < Ft) xbuf[tid] = __ldg(xb + tid);
    __syncthreads();

    if (wid < 24) {
        // ================= MAIN GROUP: recurrence =================
        float syn1 = 0.f, mem1 = 0.f, spk1 = 0.f;
        float syn2 = 0.f, mem2 = 0.f, spk2 = 0.f;
        float b1r = 0.f, be1 = 0.f, b2r = 0.f, be2 = 0.f;
        const int h2 = tid - 256;
        if (tid < Ht)           { b1r = b1[tid]; be1 = beta1[tid]; }
        if (h2 >= 0 && h2 < Ht) { b2r = b2[h2];  be2 = beta2[h2]; }

        for (int t = 0; t <= Tt; t++) {
            const int p = t & 1, q = p ^ 1;

            float xnext = 0.f;
            if (tid < Ft && t + 1 < Tt) xnext = __ldg(xb + (t + 1) * Ft + tid);

            // ---- gather phase (three matrices concurrently) ----
            if (wid < 8) {                      // V1 rows over l1[q] -> PA
                if (t < Tt) {
                    const int n = n1c[q];
                    const int* lst = l1 + q * 256;
                    const float* base = g_V1 + 4 * lg;
                    float4 a = make_float4(0.f, 0.f, 0.f, 0.f);
                    #pragma unroll 8
                    for (int j = g; j < n; j += 4) {
                        float4 v = __ldg((const float4*)(base + (lst[j] << 8)));
                        a.x += v.x; a.y += v.y; a.z += v.z; a.w += v.w;
                    }
                    *(float4*)(PA + g * 256 + 4 * lg) = a;
                }
            } else if (wid < 16) {              // W2T rows over l1[q] -> PC
                if (t >= 1) {
                    const int n = n1c[q];
                    const int* lst = l1 + q * 256;
                    const float* base = g_W2T + 4 * lg;
                    float4 a = make_float4(0.f, 0.f, 0.f, 0.f);
                    #pragma unroll 8
                    for (int j = g; j < n; j += 4) {
                        float4 v = __ldg((const float4*)(base + (lst[j] << 8)));
                        a.x += v.x; a.y += v.y; a.z += v.z; a.w += v.w;
                    }
                    *(float4*)(PC + g * 256 + 4 * lg) = a;
                }
            } else {                            // V2 rows over l2r[(t-2)&3] -> PB
                if (t >= 2) {
                    const int s2 = (t - 2) & 3;
                    const int n = n2r[s2];
                    const int* lst = l2r + s2 * 256;
                    const float* base = g_V2 + 4 * lg;
                    float4 a = make_float4(0.f, 0.f, 0.f, 0.f);
                    #pragma unroll 8
                    for (int j = g; j < n; j += 4) {
                        float4 v = __ldg((const float4*)(base + (lst[j] << 8)));
                        a.x += v.x; a.y += v.y; a.z += v.z; a.w += v.w;
                    }
                    *(float4*)(PB + g * 256 + 4 * lg) = a;
                }
            }
            BSYNC(12, 768);                                   // partials ready
            if (tid < Ft && t + 1 < Tt) xbuf[q * Ft + tid] = xnext;

            // ---- layer1 step t (warps 0-7) ----
            if (wid < 8) {
                if (t < Tt) {
                    const float* xt = xbuf + p * Ft;
                    float a0 = b1r, a1 = 0.f, a2 = 0.f, a3 = 0.f;
                    #pragma unroll
                    for (int f = 0; f < 5; f++) {
                        a0 = fmaf(xt[f],      w1t[f * Ht + tid],        a0);
                        a1 = fmaf(xt[f + 5],  w1t[(f + 5) * Ht + tid],  a1);
                        a2 = fmaf(xt[f + 10], w1t[(f + 10) * Ht + tid], a2);
                        a3 = fmaf(xt[f + 15], w1t[(f + 15) * Ht + tid], a3);
                    }
                    float wx = (a0 + a1) + (a2 + a3);
                    float s = ((PA[tid] + PA[256 + tid]) + (PA[512 + tid] + PA[768 + tid]));
                    syn1 = 0.95f * syn1 + (wx + s);
                    mem1 = be1 * mem1 + syn1 - spk1;          // THR=1, detached reset
                    spk1 = (mem1 - 1.0f) > 0.f ? 1.f : 0.f;

                    unsigned bal = __ballot_sync(0xffffffffu, spk1 != 0.f);
                    if (lane == 0) wc1[wid] = __popc(bal);
                    BSYNC(1, 256);
                    int off = 0, tot = 0;
                    #pragma unroll
                    for (int w = 0; w < 8; w++) { int c = wc1[w]; off += (w < wid) ? c : 0; tot += c; }
                    if (spk1 != 0.f) l1[p * 256 + off + __popc(bal & ((1u << lane) - 1u))] = tid;
                    if (tid == 0) n1c[p] = tot;
                }
                BSYNC(13, 512);                               // l1 handoff (w0-15)
            }
            // ---- layer2 step u=t-1 (warps 8-15), ring producer ----
            else if (wid < 16) {
                if (t >= 1) {
                    const int u = t - 1, s = u & 3;
                    const int w2 = wid - 8;
                    float sacc = ((PC[h2] + PC[256 + h2]) + (PC[512 + h2] + PC[768 + h2])) +
                                 ((PB[h2] + PB[256 + h2]) + (PB[512 + h2] + PB[768 + h2]));
                    syn2 = 0.95f * syn2 + (b2r + sacc);
                    mem2 = be2 * mem2 + syn2 - spk2;
                    spk2 = (mem2 - 1.0f) > 0.f ? 1.f : 0.f;

                    unsigned bal = __ballot_sync(0xffffffffu, spk2 != 0.f);
                    if (lane == 0) wc2[w2] = __popc(bal);
                    BSYNC(3, 256);
                    int off = 0, tot = 0;
                    #pragma unroll
                    for (int w = 0; w < 8; w++) { int c = wc2[w]; off += (w < w2) ? c : 0; tot += c; }
                    if (u >= 4) BSYNC(8 + s, 512);            // free[s]: readout done with slot
                    if (spk2 != 0.f) l2r[s * 256 + off + __popc(bal & ((1u << lane) - 1u))] = h2;
                    if (h2 == 0) n2r[s] = tot;
                    __threadfence_block();
                    BARRIVE(4 + s, 512);                      // full[s]: slot published
                }
                BSYNC(13, 512);                               // l1 handoff (w0-15)
                BSYNC(14, 512);                               // l2 handoff (w8-23)
            }
            // ---- warps 16-23 ----
            else {
                BSYNC(14, 512);                               // l2 handoff (w8-23)
            }
        }
    } else {
        // ================= READOUT GROUP (decoupled, lags 1-3 steps) =================
        const int rtid = tid - 768;            // 0..255
        const int rg   = (tid >> 6) & 3;
        const int rlg  = tid & 63;
        const int rwid = wid - 24;             // 0..7
        float synO = 0.f, memO = 0.f, spkO = 0.f, accO = 0.f;
        float aOr = 0.f, bOr = 0.f;
        if (rtid < Ot) { aOr = alpha_out[rtid]; bOr = beta_out[rtid]; }

        for (int tau = 0; tau < Tt; tau++) {
            const int s = tau & 3;
            BSYNC(4 + s, 512);                 // full[s]: wait for spk2(tau) list
            const int n2 = n2r[s];
            if (rlg < 50) {                    // WoT gather (200 wide) -> PW
                const int* lst = l2r + s * 256;
                const float* base = g_WoT + 4 * rlg;
                float4 a = make_float4(0.f, 0.f, 0.f, 0.f);
                #pragma unroll 8
                for (int j = rg; j < n2; j += 4) {
                    float4 v = __ldg((const float4*)(base + lst[j] * Ot));
                    a.x += v.x; a.y += v.y; a.z += v.z; a.w += v.w;
                }
                *(float4*)(PW + rg * 256 + 4 * rlg) = a;
            }
            BARRIVE(8 + s, 512);               // free[s]: done reading l2r/n2r slot
            BSYNC(15, 256);                    // PW ready

            float mval = -3.402823e38f;
            if (rtid < Ot) {
                float o_t = ((PW[rtid] + PW[256 + rtid]) + (PW[512 + rtid] + PW[768 + rtid]));
                synO = aOr * synO + o_t;
                memO = bOr * memO + synO - spkO;
                spkO = (memO - 1.0f) > 0.f ? 1.f : 0.f;
                mval = memO;
            }
            #pragma unroll
            for (int sh = 16; sh; sh >>= 1) mval = fmaxf(mval, __shfl_xor_sync(0xffffffffu, mval, sh));
            if (lane == 0) wred[rwid] = mval;
            BSYNC(15, 256);
            float mx = fmaxf(fmaxf(fmaxf(wred[0], wred[1]), fmaxf(wred[2], wred[3])),
                             fmaxf(fmaxf(wred[4], wred[5]), wred[6]));
            float ev = (rtid < Ot) ? __expf(memO - mx) : 0.f;
            float sv = ev;
            #pragma unroll
            for (int sh = 16; sh; sh >>= 1) sv += __shfl_xor_sync(0xffffffffu, sv, sh);
            BSYNC(15, 256);
            if (lane == 0) wred[rwid] = sv;
            BSYNC(15, 256);
            float ssum = (((wred[0] + wred[1]) + (wred[2] + wred[3])) +
                          ((wred[4] + wred[5]) + wred[6]));
            if (rtid < Ot && tau > 10) accO += ev / ssum;     // step > WARMUP
        }
        if (rtid < Ot) out[b * Ot + rtid] = accO;
    }
}

extern "C" void kernel_launch(void* const* d_in, const int* in_sizes, int n_in,
                              void* d_out, int out_size) {
    const float* x         = (const float*)d_in[0];
    const float* W1        = (const float*)d_in[1];
    const float* b1        = (const float*)d_in[2];
    const float* Vrec1     = (const float*)d_in[3];
    const float* beta1     = (const float*)d_in[4];
    const float* W2        = (const float*)d_in[5];
    const float* b2        = (const float*)d_in[6];
    const float* Vrec2     = (const float*)d_in[7];
    const float* beta2     = (const float*)d_in[8];
    const float* Wout      = (const float*)d_in[9];
    const float* alpha_out = (const float*)d_in[10];
    const float* beta_out  = (const float*)d_in[11];
    float* out = (float*)d_out;

    cudaFuncSetAttribute((const void*)snn_main,
                         cudaFuncAttributeMaxDynamicSharedMemorySize, SMEM_BYTES);

    snn_prep<<<(Ht * Ht + 255) / 256, 256>>>(Vrec1, Vrec2, W2, Wout);
    snn_main<<<Bt, NTHR, SMEM_BYTES>>>(x, W1, b1, beta1, b2, beta2,
                                       alpha_out, beta_out, out);
}